// round 17
// baseline (speedup 1.0000x reference)
#include <cuda_runtime.h>
#include <cuda_fp16.h>
#include <cstdint>

#define B_ 4
#define T_ 2048
#define C_ 1024
#define H_ 16
#define D_ 64
#define M_ (B_*T_)   /* 8192 */

// ---------------- device scratch (fp16) ----------------------------------------
__device__ __half g_x[(size_t)M_*C_];
__device__ __half g_wa[(size_t)C_*3*C_];
__device__ __half g_wp[(size_t)C_*C_];
__device__ __half g_yh[(size_t)M_*C_];
__device__ __half g_q[(size_t)M_*C_];
__device__ __half g_k[(size_t)M_*C_];
__device__ __half g_v[(size_t)M_*C_];

// ---------------- helpers ------------------------------------------------------
__device__ __forceinline__ uint32_t s2u(const void* p) {
    return (uint32_t)__cvta_generic_to_shared(p);
}
__device__ __forceinline__ void cpa16(uint32_t dst, const void* src) {
    asm volatile("cp.async.cg.shared.global [%0], [%1], 16;" :: "r"(dst), "l"(src));
}
#define CP_COMMIT() asm volatile("cp.async.commit_group;" ::: "memory")
#define CP_WAIT0()  asm volatile("cp.async.wait_group 0;" ::: "memory")
#define CP_WAIT2()  asm volatile("cp.async.wait_group 2;" ::: "memory")

#define LDM_X4(r, addr) \
    asm volatile("ldmatrix.sync.aligned.m8n8.x4.shared.b16 {%0,%1,%2,%3},[%4];" \
        : "=r"((r)[0]), "=r"((r)[1]), "=r"((r)[2]), "=r"((r)[3]) : "r"(addr))
#define LDM_X4T(r, addr) \
    asm volatile("ldmatrix.sync.aligned.m8n8.x4.trans.shared.b16 {%0,%1,%2,%3},[%4];" \
        : "=r"((r)[0]), "=r"((r)[1]), "=r"((r)[2]), "=r"((r)[3]) : "r"(addr))

#define MMA16816(d, a, b) \
    asm volatile("mma.sync.aligned.m16n8k16.row.col.f32.f16.f16.f32 " \
        "{%0,%1,%2,%3},{%4,%5,%6,%7},{%8,%9},{%0,%1,%2,%3};" \
        : "+f"((d)[0]), "+f"((d)[1]), "+f"((d)[2]), "+f"((d)[3]) \
        : "r"((a)[0]), "r"((a)[1]), "r"((a)[2]), "r"((a)[3]), \
          "r"((b)[0]), "r"((b)[1]))

__device__ __forceinline__ float ex2f(float x) {
    float y;
    asm("ex2.approx.f32 %0, %1;" : "=f"(y) : "f"(x));
    return y;
}
__device__ __forceinline__ uint32_t ex2h2(uint32_t x) {
    uint32_t y;
    asm("ex2.approx.f16x2 %0, %1;" : "=r"(y) : "r"(x));
    return y;
}

__device__ __forceinline__ uint32_t pack_h2(float a, float b) {
    __half2 v = __floats2half2_rn(a, b);
    return *(uint32_t*)&v;
}

// q pre-scale: 1/sqrt(D) * log2(e)
#define QSCALE 0.1803368801111306f

// ---------------- merged preprocessing (8 fp32 -> 8 fp16 per thread) ------------
#define NX8  (M_*C_/8)
#define NWA8 (3*C_*C_/8)
#define NWP8 (C_*C_/8)

__global__ void preprocess_kernel(const float* __restrict__ x,
                                  const float* __restrict__ wa,
                                  const float* __restrict__ wp)
{
    int i = blockIdx.x * blockDim.x + threadIdx.x;
    const float* src;
    __half* dst;
    int j;
    if (i < NX8)                  { src = x;  dst = g_x;  j = i; }
    else if (i < NX8 + NWA8)      { src = wa; dst = g_wa; j = i - NX8; }
    else if (i < NX8 + NWA8 + NWP8){ src = wp; dst = g_wp; j = i - NX8 - NWA8; }
    else return;
    float4 v0 = ((const float4*)src)[2*j];
    float4 v1 = ((const float4*)src)[2*j + 1];
    ((uint4*)dst)[j] = make_uint4(pack_h2(v0.x, v0.y), pack_h2(v0.z, v0.w),
                                  pack_h2(v1.x, v1.y), pack_h2(v1.z, v1.w));
}

// ---------------- fp16 GEMM: warp tile 64x64, 4 warps (128 thr), BK=16, 4-stage -
#define BM 128
#define BN 128
#define BK 16
#define AST 24
#define BST 136
#define KTILES (C_/BK)          /* 64 */
#define STAGES 4
#define ASZ (BM*AST*2)
#define BSZ (BK*BST*2)
#define STG (ASZ + BSZ)
#define GEMM_SMEM (STAGES*STG)  /* 41984 B */

template<bool SCATTER>
__global__ __launch_bounds__(128, 2) void gemm_fp16(
    const float* __restrict__ bias, float* __restrict__ out)
{
    extern __shared__ char dsm[];
    const uint32_t base = s2u(dsm);

    const __half* Ag = SCATTER ? g_x : g_yh;
    const __half* Bg = SCATTER ? g_wa : g_wp;
    const int NSTR = SCATTER ? 3*C_ : C_;

    const int K = C_;
    const int tid  = threadIdx.x;
    const int lane = tid & 31, wid = tid >> 5;
    const int wr = wid >> 1, wc = wid & 1;       // 2x2 warp grid, warp tile 64x64
    const int row0 = blockIdx.y * BM, col0 = blockIdx.x * BN;

    // global-load assignment (128 threads)
    const int rA = tid;              // A: 128 rows, 2 chunks each
    const int rB = tid >> 3;         // B: 16 rows x 8 chunk-pairs
    const int cB = tid & 7;

    const __half* srcA = Ag + (size_t)(row0 + rA) * K;
    const __half* srcB = Bg + (size_t)rB * NSTR + col0 + cB * 8;

    const uint32_t offA0 = (uint32_t)(rA*AST) * 2;
    const uint32_t offA1 = (uint32_t)(rA*AST + 8) * 2;
    const uint32_t offB0 = (uint32_t)(rB*BST + cB*8) * 2;
    const uint32_t offB1 = (uint32_t)(rB*BST + (cB+8)*8) * 2;

    auto load_stage = [&](int kt, int buf) {
        const uint32_t sb = base + buf * STG;
        cpa16(sb + offA0, srcA + kt * BK);
        cpa16(sb + offA1, srcA + kt * BK + 8);
        cpa16(sb + ASZ + offB0, srcB + (size_t)kt * BK * NSTR);
        cpa16(sb + ASZ + offB1, srcB + (size_t)kt * BK * NSTR + 64);
    };

    const int lm = lane & 15, lh = lane >> 4;
    const uint32_t aOff = (uint32_t)((wr*64 + lm) * AST + lh * 8) * 2;
    const uint32_t bOff = (uint32_t)(lm * BST + (wc*64 + lh*8)) * 2;

    float acc[4][8][4];
#pragma unroll
    for (int mi = 0; mi < 4; mi++)
#pragma unroll
        for (int ni = 0; ni < 8; ni++)
#pragma unroll
            for (int r = 0; r < 4; r++) acc[mi][ni][r] = 0.f;

    auto compute = [&](int buf) {
        const uint32_t sb = base + buf * STG;
        const uint32_t aA = sb + aOff;
        const uint32_t bB = sb + ASZ + bOff;
        uint32_t aa[4][4], bb[8][2], r[4];
#pragma unroll
        for (int mi = 0; mi < 4; mi++) LDM_X4(aa[mi], aA + mi * (16*AST*2));
#pragma unroll
        for (int g = 0; g < 4; g++) {
            LDM_X4T(r, bB + g * 32);
            bb[2*g][0]   = r[0]; bb[2*g][1]   = r[1];
            bb[2*g+1][0] = r[2]; bb[2*g+1][1] = r[3];
        }
#pragma unroll
        for (int mi = 0; mi < 4; mi++)
#pragma unroll
            for (int ni = 0; ni < 8; ni++) MMA16816(acc[mi][ni], aa[mi], bb[ni]);
    };

#pragma unroll
    for (int s = 0; s < STAGES - 1; s++) {
        load_stage(s, s);
        CP_COMMIT();
    }

#pragma unroll 1
    for (int kt = 0; kt < KTILES; kt++) {
        CP_WAIT2();
        __syncthreads();
        if (kt + STAGES - 1 < KTILES)
            load_stage(kt + STAGES - 1, (kt + STAGES - 1) & (STAGES - 1));
        CP_COMMIT();
        compute(kt & (STAGES - 1));
    }

    // ---------------- epilogue ----------------
    const int ncol0 = col0 + wc * 64;

#pragma unroll
    for (int ni = 0; ni < 8; ni++) {
        const int n = ncol0 + ni*8 + (lane & 3) * 2;
        const float b0 = bias[n], b1 = bias[n + 1];
        if (SCATTER) {
            const int which = n / C_;
            const int c0 = n % C_;
            const int hh = c0 / D_, d0 = c0 % D_;
            const float sc = (which == 0) ? QSCALE : 1.0f;
            __half* dst = (which == 0) ? g_q : (which == 1) ? g_k : g_v;
#pragma unroll
            for (int mi = 0; mi < 4; mi++) {
                const int m = row0 + wr*64 + mi*16 + (lane >> 2);
                const int b = m / T_, t = m % T_;
                const size_t bse = (((size_t)(b*H_ + hh)) * T_ + t) * D_ + d0;
                *(uint32_t*)&dst[bse] =
                    pack_h2((acc[mi][ni][0] + b0) * sc, (acc[mi][ni][1] + b1) * sc);
                *(uint32_t*)&dst[bse + 8*D_] =
                    pack_h2((acc[mi][ni][2] + b0) * sc, (acc[mi][ni][3] + b1) * sc);
            }
        } else {
#pragma unroll
            for (int mi = 0; mi < 4; mi++) {
                const int m = row0 + wr*64 + mi*16 + (lane >> 2);
                *(float2*)&out[(size_t)m * C_ + n] =
                    make_float2(acc[mi][ni][0] + b0, acc[mi][ni][1] + b1);
                *(float2*)&out[(size_t)(m + 8) * C_ + n] =
                    make_float2(acc[mi][ni][2] + b0, acc[mi][ni][3] + b1);
            }
        }
    }
}

// ---------------- fp16 flash attention (R16-measured, unchanged) ----------------
#define ATT_PITCH 72
#define KV_ARR (64*ATT_PITCH*2)
#define KV_STG (2*KV_ARR)
#define ATT_SMEM (2*KV_STG)

__global__ __launch_bounds__(256, 2) void attn_mma_kernel()
{
    extern __shared__ char dsm[];
    const uint32_t base = s2u(dsm);
    __half* smp = (__half*)dsm;

    const int b = blockIdx.z, h = blockIdx.y;
    const int qt = gridDim.x - 1 - blockIdx.x;   // longest-first
    const int q0 = qt * 128;
    const int tid = threadIdx.x, lane = tid & 31, wid = tid >> 5;
    const size_t hb = ((size_t)(b*H_ + h)) * T_ * D_;

    {
        const int row = tid >> 1, cg = (tid & 1) * 32;
        const uint4* s4 = (const uint4*)(g_q + hb + (size_t)(q0+row)*D_ + cg);
        uint4* d4 = (uint4*)(smp + row*ATT_PITCH + cg);
#pragma unroll
        for (int i = 0; i < 4; i++) d4[i] = s4[i];
    }
    __syncthreads();

    uint32_t qf[4][4];
    {
        const int qr = lane & 15, qc = (lane & 16) >> 1;
        const uint32_t baseQ = base + (uint32_t)((wid*16 + qr)*ATT_PITCH + qc) * 2;
#pragma unroll
        for (int kk = 0; kk < 4; kk++)
            LDM_X4(qf[kk], baseQ + kk * 32);
    }
    __syncthreads();

    float o[8][4];
#pragma unroll
    for (int n = 0; n < 8; n++)
#pragma unroll
        for (int r = 0; r < 4; r++) o[n][r] = 0.f;
    float la[4] = {0.f, 0.f, 0.f, 0.f};
    float m0 = -1e30f, m1 = -1e30f;
    const uint32_t ones2[2] = {0x3C003C00u, 0x3C003C00u};

    const int kbrow = (lane & 7) + ((lane & 16) >> 1);
    const int kbcol = (lane & 8);
    const int vrow  = lane & 15;
    const int vcolg = (lane & 16) >> 1;
    const uint32_t kOff = (uint32_t)(kbrow*ATT_PITCH + kbcol) * 2;
    const uint32_t vOff = KV_ARR + (uint32_t)(vrow*ATT_PITCH + vcolg) * 2;

    const int kvr = tid >> 3, kvc = (tid & 7) * 8;
    const uint32_t dOff = (uint32_t)(kvr*ATT_PITCH + kvc) * 2;
    const uint32_t rstep = 32*ATT_PITCH*2;

    auto load_tile = [&](int k0, int buf) {
        const uint32_t sb = base + buf * KV_STG;
        const size_t g = hb + (size_t)(k0 + kvr)*D_ + kvc;
        cpa16(sb + dOff,                  g_k + g);
        cpa16(sb + dOff + rstep,          g_k + g + 32*D_);
        cpa16(sb + KV_ARR + dOff,         g_v + g);
        cpa16(sb + KV_ARR + dOff + rstep, g_v + g + 32*D_);
    };

    const int row_lo = q0 + wid*16 + (lane >> 2);
    const int row_hi_warp = q0 + wid*16 + 15;
    const int ntiles = q0/64 + 2;

    load_tile(0, 0);
    CP_COMMIT();

#pragma unroll 1
    for (int t = 0; t < ntiles; t++) {
        const int k0 = t * 64;
        const uint32_t sb = base + (t & 1) * KV_STG;

        CP_WAIT0();
        __syncthreads();
        if (t + 1 < ntiles) {
            load_tile(k0 + 64, (t + 1) & 1);
            CP_COMMIT();
        }

        if (k0 <= row_hi_warp) {

        float s[8][4];
#pragma unroll
        for (int n = 0; n < 8; n++)
#pragma unroll
            for (int r = 0; r < 4; r++) s[n][r] = 0.f;

#pragma unroll
        for (int kk = 0; kk < 4; kk++) {
            uint32_t kf[4][4];
#pragma unroll
            for (int np = 0; np < 4; np++)
                LDM_X4(kf[np], sb + kOff + (uint32_t)(np*16*ATT_PITCH)*2 + kk*32);
#pragma unroll
            for (int np = 0; np < 4; np++) {
                MMA16816(s[2*np],   qf[kk], kf[np]);
                MMA16816(s[2*np+1], qf[kk], kf[np]+2);
            }
        }

        if (k0 + 64 > q0) {
#pragma unroll
            for (int n = 0; n < 8; n++) {
                const int c = k0 + n*8 + 2*(lane & 3);
                if (c     > row_lo)     s[n][0] = -1e30f;
                if (c + 1 > row_lo)     s[n][1] = -1e30f;
                if (c     > row_lo + 8) s[n][2] = -1e30f;
                if (c + 1 > row_lo + 8) s[n][3] = -1e30f;
            }
        }

        float tm0 = -1e30f, tm1 = -1e30f;
#pragma unroll
        for (int n = 0; n < 8; n++) {
            tm0 = fmaxf(tm0, fmaxf(s[n][0], s[n][1]));
            tm1 = fmaxf(tm1, fmaxf(s[n][2], s[n][3]));
        }
        tm0 = fmaxf(tm0, __shfl_xor_sync(0xffffffff, tm0, 1));
        tm0 = fmaxf(tm0, __shfl_xor_sync(0xffffffff, tm0, 2));
        tm1 = fmaxf(tm1, __shfl_xor_sync(0xffffffff, tm1, 1));
        tm1 = fmaxf(tm1, __shfl_xor_sync(0xffffffff, tm1, 2));

        if (tm0 > m0) {
            const float c0 = ex2f(m0 - tm0);
            m0 = tm0;
            la[0] *= c0;
#pragma unroll
            for (int n = 0; n < 8; n++) { o[n][0] *= c0; o[n][1] *= c0; }
        }
        if (tm1 > m1) {
            const float c1 = ex2f(m1 - tm1);
            m1 = tm1;
            la[2] *= c1;
#pragma unroll
            for (int n = 0; n < 8; n++) { o[n][2] *= c1; o[n][3] *= c1; }
        }

        uint32_t pah[4][4];
#pragma unroll
        for (int j = 0; j < 4; j++) {
            pah[j][0] = ex2h2(pack_h2(s[2*j][0]   - m0, s[2*j][1]   - m0));
            pah[j][1] = ex2h2(pack_h2(s[2*j][2]   - m1, s[2*j][3]   - m1));
            pah[j][2] = ex2h2(pack_h2(s[2*j+1][0] - m0, s[2*j+1][1] - m0));
            pah[j][3] = ex2h2(pack_h2(s[2*j+1][2] - m1, s[2*j+1][3] - m1));
        }

#pragma unroll
        for (int kk = 0; kk < 4; kk++)
            MMA16816(la, pah[kk], ones2);

#pragma unroll
        for (int kk = 0; kk < 4; kk++) {
            uint32_t vf[4][4];
#pragma unroll
            for (int nc = 0; nc < 4; nc++)
                LDM_X4T(vf[nc], sb + vOff + (uint32_t)(kk*16*ATT_PITCH)*2 + nc*32);
#pragma unroll
            for (int nc = 0; nc < 4; nc++) {
                MMA16816(o[2*nc],   pah[kk], vf[nc]);
                MMA16816(o[2*nc+1], pah[kk], vf[nc]+2);
            }
        }

        }
    }

    const float inv0 = 1.f / la[0], inv1 = 1.f / la[2];
    const int r0 = row_lo, r1 = row_lo + 8;
#pragma unroll
    for (int n = 0; n < 8; n++) {
        const int d = n*8 + 2*(lane & 3);
        const size_t y0 = ((size_t)(b*T_ + r0))*C_ + h*D_ + d;
        const size_t y1 = ((size_t)(b*T_ + r1))*C_ + h*D_ + d;
        *(uint32_t*)&g_yh[y0] = pack_h2(o[n][0]*inv0, o[n][1]*inv0);
        *(uint32_t*)&g_yh[y1] = pack_h2(o[n][2]*inv1, o[n][3]*inv1);
    }
}

// -------------------------------------------------------------------------------
extern "C" void kernel_launch(void* const* d_in, const int* in_sizes, int n_in,
                              void* d_out, int out_size)
{
    const float* x      = (const float*)d_in[0];
    const float* w_attn = (const float*)d_in[1];
    const float* b_attn = (const float*)d_in[2];
    const float* w_proj = (const float*)d_in[3];
    const float* b_proj = (const float*)d_in[4];
    float* out = (float*)d_out;

    cudaFuncSetAttribute(gemm_fp16<true>,
        cudaFuncAttributeMaxDynamicSharedMemorySize, GEMM_SMEM);
    cudaFuncSetAttribute(gemm_fp16<false>,
        cudaFuncAttributeMaxDynamicSharedMemorySize, GEMM_SMEM);
    cudaFuncSetAttribute(attn_mma_kernel,
        cudaFuncAttributeMaxDynamicSharedMemorySize, ATT_SMEM);

    {
        int total = NX8 + NWA8 + NWP8;
        preprocess_kernel<<<(total + 255) / 256, 256>>>(x, w_attn, w_proj);
    }

    dim3 g1(3 * C_ / BN, M_ / BM);   // (24, 64)
    gemm_fp16<true><<<g1, 128, GEMM_SMEM>>>(b_attn, nullptr);

    dim3 g2(T_ / 128, H_, B_);       // (16, 16, 4)
    attn_mma_kernel<<<g2, 256, ATT_SMEM>>>();

    dim3 g3(C_ / BN, M_ / BM);       // (8, 64)
    gemm_fp16<false><<<g3, 128, GEMM_SMEM>>>(b_proj, out);
}